// round 4
// baseline (speedup 1.0000x reference)
#include <cuda_runtime.h>

#define IHH 36      // padded tile height
#define SW  38      // padded width for sb/sd/sz (36 used)
#define HW  34      // row width for hb/hd (32 used)

__device__ __forceinline__ float frcp(float x){ float y; asm("rcp.approx.ftz.f32 %0,%1;":"=f"(y):"f"(x)); return y; }
__device__ __forceinline__ float fex2(float x){ float y; asm("ex2.approx.ftz.f32 %0,%1;":"=f"(y):"f"(x)); return y; }
__device__ __forceinline__ float flg2(float x){ float y; asm("lg2.approx.ftz.f32 %0,%1;":"=f"(y):"f"(x)); return y; }

__global__ __launch_bounds__(256, 5)
void bilateral_kernel(const float* __restrict__ bright,
                      const float* __restrict__ dark,
                      const float* __restrict__ depths,
                      const float* __restrict__ s_dv,
                      const float* __restrict__ s_sv,
                      const float* __restrict__ s_de,
                      const float* __restrict__ s_eps,
                      const float* __restrict__ s_ce,
                      float* __restrict__ out)
{
    __shared__ float sb[IHH][SW];
    __shared__ float sd[IHH][SW];
    __shared__ float sz[IHH][SW];
    __shared__ float hb[IHH][HW];
    __shared__ float hd[IHH][HW];

    const int tid = threadIdx.x;
    const int x0 = blockIdx.x * 32;
    const int y0 = blockIdx.y * 32;
    const size_t base = (size_t)blockIdx.z * (1024 * 1024);

    const float log2e = 1.44269504f;
    const float c2l = -0.5f * frcp(s_dv[0]) * log2e;
    const float svl = -0.5f * frcp(s_sv[0]) * log2e;
    const float swl[5] = {4.f*svl, 1.f*svl, 0.f, 1.f*svl, 4.f*svl};

    // ---------- Phase 1: load padded tiles ----------
    {
        const int tx = tid & 31;
        const int tyL = tid >> 5;                 // 0..7
        const bool interior = (blockIdx.x >= 1) & (blockIdx.x <= 30) &
                              (blockIdx.y >= 1) & (blockIdx.y <= 30);
        if (interior) {
            // no bounds checks: whole 36x36 halo tile is in-image
            #pragma unroll
            for (int r = tyL; r < IHH; r += 8) {
                const size_t rowbase = base + (size_t)(y0 + r - 2) * 1024 + x0 - 2;
                sb[r][tx] = bright[rowbase + tx];
                sd[r][tx] = dark[rowbase + tx];
                sz[r][tx] = depths[rowbase + tx];
                if (tx < 4) {
                    const int c = tx + 32;
                    sb[r][c] = bright[rowbase + c];
                    sd[r][c] = dark[rowbase + c];
                    sz[r][c] = depths[rowbase + c];
                }
            }
        } else {
            #pragma unroll
            for (int r = tyL; r < IHH; r += 8) {
                const int gy = y0 + r - 2;
                const bool yin = (unsigned)gy < 1024u;
                const size_t rowbase = base + (size_t)gy * 1024;
                {
                    const int gx = x0 + tx - 2;
                    const bool in = yin && ((unsigned)gx < 1024u);
                    const size_t gi = rowbase + gx;
                    sb[r][tx] = in ? bright[gi] : 0.0f;
                    sd[r][tx] = in ? dark[gi]   : 0.0f;
                    sz[r][tx] = in ? depths[gi] : 0.0f;
                }
                if (tx < 4) {
                    const int c = tx + 32;
                    const int gx = x0 + c - 2;
                    const bool in = yin && ((unsigned)gx < 1024u);
                    const size_t gi = rowbase + gx;
                    sb[r][c] = in ? bright[gi] : 0.0f;
                    sd[r][c] = in ? dark[gi]   : 0.0f;
                    sz[r][c] = in ? depths[gi] : 0.0f;
                }
            }
        }
    }
    __syncthreads();

    const int txh = tid & 15;        // 16 col-groups of 2 px
    const int tyh = tid >> 4;        // 0..15
    const int c = txh * 2;           // output cols c, c+1

    // ---------- Phase 2: horizontal blur over 36 padded rows ----------
    for (int r = tyh; r < IHH; r += 16) {
        const int gy = y0 + r - 2;
        const bool valid = (unsigned)gy < 1024u;

        float2 z0 = *(const float2*)&sz[r][c];
        float2 z1 = *(const float2*)&sz[r][c + 2];
        float2 z2 = *(const float2*)&sz[r][c + 4];
        float2 b0 = *(const float2*)&sb[r][c];
        float2 b1 = *(const float2*)&sb[r][c + 2];
        float2 b2 = *(const float2*)&sb[r][c + 4];
        float2 d0 = *(const float2*)&sd[r][c];
        float2 d1 = *(const float2*)&sd[r][c + 2];
        float2 d2 = *(const float2*)&sd[r][c + 4];
        const float za[6] = {z0.x, z0.y, z1.x, z1.y, z2.x, z2.y};
        const float ba[6] = {b0.x, b0.y, b1.x, b1.y, b2.x, b2.y};
        const float da[6] = {d0.x, d0.y, d1.x, d1.y, d2.x, d2.y};

        float ob[2], od[2];
        #pragma unroll
        for (int i = 0; i < 2; i++) {
            const float rz = frcp(za[i + 2]);
            float ws = 0.f, bs = 0.f, ds = 0.f;
            #pragma unroll
            for (int k = 0; k < 5; k++) {
                const float u = fmaf(za[i + k], rz, -1.0f);
                const float a = __saturatef(u * u);       // = min(rel,1)^2
                const float w = fex2(fmaf(a, c2l, swl[k]));
                ws += w;
                bs = fmaf(w, ba[i + k], bs);
                ds = fmaf(w, da[i + k], ds);
            }
            const float wi = valid ? frcp(ws) : 0.0f;
            ob[i] = bs * wi;
            od[i] = ds * wi;
        }
        *(float2*)&hb[r][c] = make_float2(ob[0], ob[1]);
        *(float2*)&hd[r][c] = make_float2(od[0], od[1]);
    }
    __syncthreads();

    // ---------- Phase 3: vertical blur + blend, 2 rows x 2 cols per thread ----------
    const float de  = s_de[0];
    const float eps = s_eps[0];
    const float ce  = s_ce[0];
    const int r0 = 2 * tyh;          // output rows r0, r0+1

    float rz0[2], rz1[2];
    {
        float2 t0 = *(const float2*)&sz[r0 + 2][c + 2];
        float2 t1 = *(const float2*)&sz[r0 + 3][c + 2];
        rz0[0] = frcp(t0.x); rz0[1] = frcp(t0.y);
        rz1[0] = frcp(t1.x); rz1[1] = frcp(t1.y);
    }

    float ws0[2] = {0,0}, bs0[2] = {0,0}, ds0[2] = {0,0};
    float ws1[2] = {0,0}, bs1[2] = {0,0}, ds1[2] = {0,0};

    #pragma unroll
    for (int j = 0; j < 6; j++) {
        const int pr = r0 + j;
        float2 zt = *(const float2*)&sz[pr][c + 2];
        float2 bt = *(const float2*)&hb[pr][c];
        float2 dt = *(const float2*)&hd[pr][c];
        const float zv[2] = {zt.x, zt.y};
        const float bv[2] = {bt.x, bt.y};
        const float dv[2] = {dt.x, dt.y};

        if (j < 5) {
            const float sl = swl[j];
            #pragma unroll
            for (int i = 0; i < 2; i++) {
                const float u = fmaf(zv[i], rz0[i], -1.0f);
                const float a = __saturatef(u * u);
                const float w = fex2(fmaf(a, c2l, sl));
                ws0[i] += w;
                bs0[i] = fmaf(w, bv[i], bs0[i]);
                ds0[i] = fmaf(w, dv[i], ds0[i]);
            }
        }
        if (j >= 1) {
            const float sl = swl[j - 1];
            #pragma unroll
            for (int i = 0; i < 2; i++) {
                const float u = fmaf(zv[i], rz1[i], -1.0f);
                const float a = __saturatef(u * u);
                const float w = fex2(fmaf(a, c2l, sl));
                ws1[i] += w;
                bs1[i] = fmaf(w, bv[i], bs1[i]);
                ds1[i] = fmaf(w, dv[i], ds1[i]);
            }
        }
    }

    #pragma unroll
    for (int rr = 0; rr < 2; rr++) {
        const int orow = r0 + rr;
        const float* wsA = rr ? ws1 : ws0;
        const float* bsA = rr ? bs1 : bs0;
        const float* dsA = rr ? ds1 : ds0;

        float2 bc = *(const float2*)&sb[orow + 2][c + 2];
        float2 dc = *(const float2*)&sd[orow + 2][c + 2];
        const float bca[2] = {bc.x, bc.y};
        const float dca[2] = {dc.x, dc.y};

        float o[2];
        #pragma unroll
        for (int i = 0; i < 2; i++) {
            const float wi = frcp(wsA[i]);
            const float bmean = bsA[i] * wi;
            const float dmean = dsA[i] * wi;
            const float bv = bca[i];
            const float dk = dca[i];
            float devb = fex2(de * flg2(fmaxf(fabsf(bv - bmean), 1e-8f))) * ce;
            float devd = fmaxf(fex2(de * flg2(fmaxf(fabsf(dk - dmean), 1e-8f))), eps);
            o[i] = (devd * bv + devb * dk) * frcp(devb + devd);
        }
        *(float2*)&out[base + (size_t)(y0 + orow) * 1024 + x0 + c] =
            make_float2(o[0], o[1]);
    }
}

extern "C" void kernel_launch(void* const* d_in, const int* in_sizes, int n_in,
                              void* d_out, int out_size)
{
    const float* bright = (const float*)d_in[0];
    const float* dark   = (const float*)d_in[1];
    const float* depths = (const float*)d_in[2];
    const float* s_dv   = (const float*)d_in[3];
    const float* s_sv   = (const float*)d_in[4];
    const float* s_de   = (const float*)d_in[5];
    const float* s_eps  = (const float*)d_in[6];
    const float* s_ce   = (const float*)d_in[7];
    float* out = (float*)d_out;

    const int B = in_sizes[0] / (1024 * 1024);
    dim3 grid(1024 / 32, 1024 / 32, B);
    bilateral_kernel<<<grid, 256>>>(bright, dark, depths,
                                    s_dv, s_sv, s_de, s_eps, s_ce, out);
}

// round 5
// speedup vs baseline: 1.5083x; 1.5083x over previous
#include <cuda_runtime.h>

#define IHH 36      // padded tile height
#define SW  38      // padded width for sb/sd/sz (36 used)
#define HW  34      // row width for hb/hd (32 used)

__device__ __forceinline__ float frcp(float x){ float y; asm("rcp.approx.ftz.f32 %0,%1;":"=f"(y):"f"(x)); return y; }
__device__ __forceinline__ float fex2(float x){ float y; asm("ex2.approx.ftz.f32 %0,%1;":"=f"(y):"f"(x)); return y; }
__device__ __forceinline__ float flg2(float x){ float y; asm("lg2.approx.ftz.f32 %0,%1;":"=f"(y):"f"(x)); return y; }

__global__ __launch_bounds__(256, 4)
void bilateral_kernel(const float* __restrict__ bright,
                      const float* __restrict__ dark,
                      const float* __restrict__ depths,
                      const float* __restrict__ s_dv,
                      const float* __restrict__ s_sv,
                      const float* __restrict__ s_de,
                      const float* __restrict__ s_eps,
                      const float* __restrict__ s_ce,
                      float* __restrict__ out)
{
    __shared__ float sb[IHH][SW];
    __shared__ float sd[IHH][SW];
    __shared__ float sz[IHH][SW];
    __shared__ float hb[IHH][HW];
    __shared__ float hd[IHH][HW];

    const int tid = threadIdx.x;
    const int x0 = blockIdx.x * 32;
    const int y0 = blockIdx.y * 32;
    const size_t base = (size_t)blockIdx.z * (1024 * 1024);

    const float log2e = 1.44269504f;
    const float c2l = -0.5f * frcp(s_dv[0]) * log2e;
    const float svl = -0.5f * frcp(s_sv[0]) * log2e;
    const float swl[5] = {4.f*svl, 1.f*svl, 0.f, 1.f*svl, 4.f*svl};

    // ---------- Phase 1: load padded tiles ----------
    {
        const int tx = tid & 31;
        const int tyL = tid >> 5;                 // 0..7
        const bool interior = (blockIdx.x >= 1) & (blockIdx.x <= 30) &
                              (blockIdx.y >= 1) & (blockIdx.y <= 30);
        if (interior) {
            // whole 36x36 halo tile is in-image: no bounds predicates
            #pragma unroll
            for (int r = tyL; r < IHH; r += 8) {
                const size_t rowbase = base + (size_t)(y0 + r - 2) * 1024 + x0 - 2;
                sb[r][tx] = bright[rowbase + tx];
                sd[r][tx] = dark[rowbase + tx];
                sz[r][tx] = depths[rowbase + tx];
                if (tx < 4) {
                    const int c = tx + 32;
                    sb[r][c] = bright[rowbase + c];
                    sd[r][c] = dark[rowbase + c];
                    sz[r][c] = depths[rowbase + c];
                }
            }
        } else {
            #pragma unroll
            for (int r = tyL; r < IHH; r += 8) {
                const int gy = y0 + r - 2;
                const bool yin = (unsigned)gy < 1024u;
                const size_t rowbase = base + (size_t)gy * 1024;
                {
                    const int gx = x0 + tx - 2;
                    const bool in = yin && ((unsigned)gx < 1024u);
                    const size_t gi = rowbase + gx;
                    sb[r][tx] = in ? bright[gi] : 0.0f;
                    sd[r][tx] = in ? dark[gi]   : 0.0f;
                    sz[r][tx] = in ? depths[gi] : 0.0f;
                }
                if (tx < 4) {
                    const int c = tx + 32;
                    const int gx = x0 + c - 2;
                    const bool in = yin && ((unsigned)gx < 1024u);
                    const size_t gi = rowbase + gx;
                    sb[r][c] = in ? bright[gi] : 0.0f;
                    sd[r][c] = in ? dark[gi]   : 0.0f;
                    sz[r][c] = in ? depths[gi] : 0.0f;
                }
            }
        }
    }
    __syncthreads();

    const int txh = tid & 15;        // 16 col-groups of 2 px
    const int tyh = tid >> 4;        // 0..15
    const int c = txh * 2;           // output cols c, c+1

    // ---------- Phase 2: horizontal blur over 36 padded rows ----------
    for (int r = tyh; r < IHH; r += 16) {
        const int gy = y0 + r - 2;
        const bool valid = (unsigned)gy < 1024u;

        float2 z0 = *(const float2*)&sz[r][c];
        float2 z1 = *(const float2*)&sz[r][c + 2];
        float2 z2 = *(const float2*)&sz[r][c + 4];
        float2 b0 = *(const float2*)&sb[r][c];
        float2 b1 = *(const float2*)&sb[r][c + 2];
        float2 b2 = *(const float2*)&sb[r][c + 4];
        float2 d0 = *(const float2*)&sd[r][c];
        float2 d1 = *(const float2*)&sd[r][c + 2];
        float2 d2 = *(const float2*)&sd[r][c + 4];
        const float za[6] = {z0.x, z0.y, z1.x, z1.y, z2.x, z2.y};
        const float ba[6] = {b0.x, b0.y, b1.x, b1.y, b2.x, b2.y};
        const float da[6] = {d0.x, d0.y, d1.x, d1.y, d2.x, d2.y};

        float ob[2], od[2];
        #pragma unroll
        for (int i = 0; i < 2; i++) {
            const float rz = frcp(za[i + 2]);
            float ws = 0.f, bs = 0.f, ds = 0.f;
            #pragma unroll
            for (int k = 0; k < 5; k++) {
                const float u = fmaf(za[i + k], rz, -1.0f);
                const float a = __saturatef(u * u);       // = min(rel,1)^2
                const float w = fex2(fmaf(a, c2l, swl[k]));
                ws += w;
                bs = fmaf(w, ba[i + k], bs);
                ds = fmaf(w, da[i + k], ds);
            }
            const float wi = valid ? frcp(ws) : 0.0f;
            ob[i] = bs * wi;
            od[i] = ds * wi;
        }
        *(float2*)&hb[r][c] = make_float2(ob[0], ob[1]);
        *(float2*)&hd[r][c] = make_float2(od[0], od[1]);
    }
    __syncthreads();

    // ---------- Phase 3: vertical blur + blend, 2 rows x 2 cols per thread ----------
    const float de  = s_de[0];
    const float eps = s_eps[0];
    const float ce  = s_ce[0];
    const int r0 = 2 * tyh;          // output rows r0, r0+1

    float rz0[2], rz1[2];
    {
        float2 t0 = *(const float2*)&sz[r0 + 2][c + 2];
        float2 t1 = *(const float2*)&sz[r0 + 3][c + 2];
        rz0[0] = frcp(t0.x); rz0[1] = frcp(t0.y);
        rz1[0] = frcp(t1.x); rz1[1] = frcp(t1.y);
    }

    float ws0[2] = {0,0}, bs0[2] = {0,0}, ds0[2] = {0,0};
    float ws1[2] = {0,0}, bs1[2] = {0,0}, ds1[2] = {0,0};

    #pragma unroll
    for (int j = 0; j < 6; j++) {
        const int pr = r0 + j;
        float2 zt = *(const float2*)&sz[pr][c + 2];
        float2 bt = *(const float2*)&hb[pr][c];
        float2 dt = *(const float2*)&hd[pr][c];
        const float zv[2] = {zt.x, zt.y};
        const float bv[2] = {bt.x, bt.y};
        const float dv[2] = {dt.x, dt.y};

        if (j < 5) {
            const float sl = swl[j];
            #pragma unroll
            for (int i = 0; i < 2; i++) {
                const float u = fmaf(zv[i], rz0[i], -1.0f);
                const float a = __saturatef(u * u);
                const float w = fex2(fmaf(a, c2l, sl));
                ws0[i] += w;
                bs0[i] = fmaf(w, bv[i], bs0[i]);
                ds0[i] = fmaf(w, dv[i], ds0[i]);
            }
        }
        if (j >= 1) {
            const float sl = swl[j - 1];
            #pragma unroll
            for (int i = 0; i < 2; i++) {
                const float u = fmaf(zv[i], rz1[i], -1.0f);
                const float a = __saturatef(u * u);
                const float w = fex2(fmaf(a, c2l, sl));
                ws1[i] += w;
                bs1[i] = fmaf(w, bv[i], bs1[i]);
                ds1[i] = fmaf(w, dv[i], ds1[i]);
            }
        }
    }

    #pragma unroll
    for (int rr = 0; rr < 2; rr++) {
        const int orow = r0 + rr;
        const float* wsA = rr ? ws1 : ws0;
        const float* bsA = rr ? bs1 : bs0;
        const float* dsA = rr ? ds1 : ds0;

        float2 bc = *(const float2*)&sb[orow + 2][c + 2];
        float2 dc = *(const float2*)&sd[orow + 2][c + 2];
        const float bca[2] = {bc.x, bc.y};
        const float dca[2] = {dc.x, dc.y};

        float o[2];
        #pragma unroll
        for (int i = 0; i < 2; i++) {
            const float wi = frcp(wsA[i]);
            const float bmean = bsA[i] * wi;
            const float dmean = dsA[i] * wi;
            const float bv = bca[i];
            const float dk = dca[i];
            float devb = fex2(de * flg2(fmaxf(fabsf(bv - bmean), 1e-8f))) * ce;
            float devd = fmaxf(fex2(de * flg2(fmaxf(fabsf(dk - dmean), 1e-8f))), eps);
            o[i] = (devd * bv + devb * dk) * frcp(devb + devd);
        }
        *(float2*)&out[base + (size_t)(y0 + orow) * 1024 + x0 + c] =
            make_float2(o[0], o[1]);
    }
}

extern "C" void kernel_launch(void* const* d_in, const int* in_sizes, int n_in,
                              void* d_out, int out_size)
{
    const float* bright = (const float*)d_in[0];
    const float* dark   = (const float*)d_in[1];
    const float* depths = (const float*)d_in[2];
    const float* s_dv   = (const float*)d_in[3];
    const float* s_sv   = (const float*)d_in[4];
    const float* s_de   = (const float*)d_in[5];
    const float* s_eps  = (const float*)d_in[6];
    const float* s_ce   = (const float*)d_in[7];
    float* out = (float*)d_out;

    const int B = in_sizes[0] / (1024 * 1024);
    dim3 grid(1024 / 32, 1024 / 32, B);
    bilateral_kernel<<<grid, 256>>>(bright, dark, depths,
                                    s_dv, s_sv, s_de, s_eps, s_ce, out);
}